// round 12
// baseline (speedup 1.0000x reference)
#include <cuda_runtime.h>
#include <cuda_bf16.h>
#include <cstdint>

// ===========================================================================
// NHWC bf16 pipeline with tensor-core (mma.sync bf16) GEMMs.
// R10: dw_k staging via 4-px register transpose + STS.128 (wavefront cut);
//      attn_k inner product in packed fma.rn.f32x2 (FMA instr halved).
// ===========================================================================

#define NPIX 65536           // per image
#define MTOT 131072L         // total pixels (batch 2)

typedef unsigned long long u64;

__device__ __align__(16) __nv_bfloat16 g_hn[MTOT * 128];    // LN outs / mgate
__device__ __align__(16) __nv_bfloat16 g_buf1[MTOT * 768];  // hidden / va / g
__device__ __align__(16) __nv_bfloat16 g_buf2[MTOT * 768];  // qkv / x1(fp32)
__device__ __align__(16) __nv_bfloat16 g_wb[180224];        // bf16 weights

__device__ __forceinline__ unsigned pack_bf(float a, float b) {
    __nv_bfloat162 h = __float22bfloat162_rn(make_float2(a, b));
    return *(unsigned*)&h;
}
__device__ __forceinline__ float2 unpack_bf(unsigned u) {
    __nv_bfloat162 h = *(__nv_bfloat162*)&u;
    return make_float2(__bfloat162float(h.x), __bfloat162float(h.y));
}
__device__ __forceinline__ uint32_t smem_u32(const void* p) {
    return (uint32_t)__cvta_generic_to_shared(p);
}
__device__ __forceinline__ void cp16(void* dst, const void* src) {
    asm volatile("cp.async.cg.shared.global [%0], [%1], 16;"
                 :: "r"(smem_u32(dst)), "l"(src));
}
// bf16x2 -> packed f32x2 (bf16 widens by <<16; no cvt needed)
__device__ __forceinline__ u64 bf2_to_f32x2(unsigned u) {
    unsigned lo = u << 16, hi = u & 0xffff0000u;
    u64 d;
    asm("mov.b64 %0, {%1,%2};" : "=l"(d) : "r"(lo), "r"(hi));
    return d;
}
#define FMA_F32X2(d, a, b) \
    asm("fma.rn.f32x2 %0, %1, %2, %0;" : "+l"(d) : "l"(a), "l"(b))

// ---------------------------------------------------------------------------
// Weight conversion fp32 -> bf16 (once per launch; tiny)
// ---------------------------------------------------------------------------
__global__ void wcvt_k(const float* __restrict__ w1, const float* __restrict__ w2,
                       const float* __restrict__ w3, const float* __restrict__ w4,
                       __nv_bfloat16* __restrict__ o)
{
    int i = blockIdx.x * 256 + threadIdx.x;
    if (i < 98304)       o[i] = __float2bfloat16(w1[i]);
    else if (i < 131072) o[i] = __float2bfloat16(w2[i - 98304]);
    else if (i < 163840) o[i] = __float2bfloat16(w3[i - 131072]);
    else if (i < 180224) o[i] = __float2bfloat16(w4[i - 163840]);
}

// ---------------------------------------------------------------------------
// LN1: x NCHW fp32 -> y NHWC bf16 (C=128).
// ---------------------------------------------------------------------------
__global__ __launch_bounds__(256) void ln1_k(const float* __restrict__ x,
                                             const float* __restrict__ g,
                                             const float* __restrict__ b,
                                             __nv_bfloat16* __restrict__ y)
{
    __shared__ __nv_bfloat16 st[256 * 18];
    int t = threadIdx.x;
    long gp0 = (long)blockIdx.x * 256;
    long gp = gp0 + t;
    int bb = (int)(gp >> 16);
    int p  = (int)(gp & 65535);
    const float* xp = x + (long)bb * 128 * NPIX + p;

    float s = 0.f, s2 = 0.f;
    for (int c = 0; c < 128; c++) {
        float v = xp[(long)c * NPIX];
        s += v; s2 += v * v;
    }
    float m = s * (1.f / 128.f);
    float r = rsqrtf(s2 * (1.f / 128.f) - m * m + 1e-6f);

    for (int c0 = 0; c0 < 128; c0 += 16) {
#pragma unroll
        for (int cc = 0; cc < 16; cc++) {
            float v = xp[(long)(c0 + cc) * NPIX];
            st[t * 18 + cc] = __float2bfloat16((v - m) * r * g[c0 + cc] + b[c0 + cc]);
        }
        __syncthreads();
        for (int it = 0; it < 8; it++) {
            int lin = it * 256 + t;
            int pl = lin >> 3, cw = lin & 7;
            unsigned v = *(unsigned*)&st[pl * 18 + cw * 2];
            *(unsigned*)(y + (gp0 + pl) * 128 + c0 + cw * 2) = v;
        }
        __syncthreads();
    }
}

// ---------------------------------------------------------------------------
// LN3: x1 NHWC fp32 -> y NHWC bf16 (C=128). Warp per pixel.
// ---------------------------------------------------------------------------
__global__ __launch_bounds__(256) void ln3_k(const float* __restrict__ x,
                                             const float* __restrict__ g,
                                             const float* __restrict__ b,
                                             __nv_bfloat16* __restrict__ y)
{
    int t = threadIdx.x, lane = t & 31, w = t >> 5;
    long p = (long)blockIdx.x * 8 + w;
    float4 v = *(const float4*)&x[p * 128 + lane * 4];
    float s = v.x + v.y + v.z + v.w;
    float s2 = v.x * v.x + v.y * v.y + v.z * v.z + v.w * v.w;
#pragma unroll
    for (int o = 16; o; o >>= 1) {
        s  += __shfl_xor_sync(0xffffffffu, s, o);
        s2 += __shfl_xor_sync(0xffffffffu, s2, o);
    }
    float m = s * (1.f / 128.f);
    float r = rsqrtf(s2 * (1.f / 128.f) - m * m + 1e-6f);
    int c = lane * 4;
    float o0 = (v.x - m) * r * g[c]     + b[c];
    float o1 = (v.y - m) * r * g[c + 1] + b[c + 1];
    float o2 = (v.z - m) * r * g[c + 2] + b[c + 2];
    float o3 = (v.w - m) * r * g[c + 3] + b[c + 3];
    uint2 u = make_uint2(pack_bf(o0, o1), pack_bf(o2, o3));
    *(uint2*)(y + p * 128 + c) = u;
}

// ---------------------------------------------------------------------------
// Tensor-core GEMM with cp.async 2-stage double buffering.
//   A: NHWC bf16 activations [M, K], B: bf16 weights [Ntot, K]
// EPI 0: bf16 out | 1: bf16 out + bias | 2: fp32 NHWC = x_nchw + S*acc |
// EPI 3: fp32 NCHW = x1_nhwc + S*acc.
// Block tile 128x128x64, 8 warps. Dynamic smem 73728 B.
// ---------------------------------------------------------------------------
template <int K, int EPI>
__global__ __launch_bounds__(256) void gemm_tc(
    const __nv_bfloat16* __restrict__ A, const __nv_bfloat16* __restrict__ B,
    const float* __restrict__ bias, const float* __restrict__ R,
    const float* __restrict__ S, void* __restrict__ Yv, int Ntot)
{
    constexpr int LDS_ = 72;
    constexpr int MATSZ = 128 * LDS_;        // 9216 elems
    constexpr int STAGE = 2 * MATSZ;         // A+B per stage
    extern __shared__ __nv_bfloat16 sm[];

    int t = threadIdx.x;
    long m0 = (long)blockIdx.x * 128;
    int n0 = blockIdx.y * 128;
    int wid = t >> 5, lane = t & 31;
    int wm = (wid & 3) * 32, wn = (wid >> 2) * 64;

    float acc[2][8][4];
#pragma unroll
    for (int i = 0; i < 2; i++)
#pragma unroll
        for (int j = 0; j < 8; j++)
#pragma unroll
            for (int q = 0; q < 4; q++) acc[i][j][q] = 0.f;

    int lrow = t >> 3, lcol = (t & 7) * 8;

    auto load_stage = [&](int k0, int s) {
        __nv_bfloat16* As_ = sm + s * STAGE;
        __nv_bfloat16* Bs_ = As_ + MATSZ;
#pragma unroll
        for (int pp = 0; pp < 4; pp++) {
            int row = pp * 32 + lrow;
            cp16(&As_[row * LDS_ + lcol], &A[(m0 + row) * K + k0 + lcol]);
            cp16(&Bs_[row * LDS_ + lcol], &B[(long)(n0 + row) * K + k0 + lcol]);
        }
        asm volatile("cp.async.commit_group;");
    };

    constexpr int NSTEP = K / 64;
    load_stage(0, 0);

#pragma unroll
    for (int st = 0; st < NSTEP; st++) {
        if (st + 1 < NSTEP) {
            load_stage((st + 1) * 64, (st + 1) & 1);
            asm volatile("cp.async.wait_group 1;");
        } else {
            asm volatile("cp.async.wait_group 0;");
        }
        __syncthreads();

        const __nv_bfloat16* As_ = sm + (st & 1) * STAGE;
        const __nv_bfloat16* Bs_ = As_ + MATSZ;

#pragma unroll
        for (int kk = 0; kk < 4; kk++) {
            uint32_t a[2][4], bf[8][2];
#pragma unroll
            for (int mi = 0; mi < 2; mi++) {
                uint32_t addr = smem_u32(
                    &As_[(wm + mi * 16 + (lane & 15)) * LDS_ + kk * 16 + (lane >> 4) * 8]);
                asm volatile("ldmatrix.sync.aligned.m8n8.x4.shared.b16 {%0,%1,%2,%3}, [%4];"
                             : "=r"(a[mi][0]), "=r"(a[mi][1]), "=r"(a[mi][2]), "=r"(a[mi][3])
                             : "r"(addr));
            }
#pragma unroll
            for (int nb = 0; nb < 4; nb++) {
                int row = wn + nb * 16 + ((lane >> 4) << 3) + (lane & 7);
                int col = kk * 16 + ((lane >> 3) & 1) * 8;
                uint32_t addr = smem_u32(&Bs_[row * LDS_ + col]);
                uint32_t r0, r1, r2, r3;
                asm volatile("ldmatrix.sync.aligned.m8n8.x4.shared.b16 {%0,%1,%2,%3}, [%4];"
                             : "=r"(r0), "=r"(r1), "=r"(r2), "=r"(r3) : "r"(addr));
                bf[nb * 2][0] = r0;     bf[nb * 2][1] = r1;
                bf[nb * 2 + 1][0] = r2; bf[nb * 2 + 1][1] = r3;
            }
#pragma unroll
            for (int mi = 0; mi < 2; mi++)
#pragma unroll
                for (int nj = 0; nj < 8; nj++) {
                    asm volatile(
                        "mma.sync.aligned.m16n8k16.row.col.f32.bf16.bf16.f32 "
                        "{%0,%1,%2,%3}, {%4,%5,%6,%7}, {%8,%9}, {%0,%1,%2,%3};"
                        : "+f"(acc[mi][nj][0]), "+f"(acc[mi][nj][1]),
                          "+f"(acc[mi][nj][2]), "+f"(acc[mi][nj][3])
                        : "r"(a[mi][0]), "r"(a[mi][1]), "r"(a[mi][2]), "r"(a[mi][3]),
                          "r"(bf[nj][0]), "r"(bf[nj][1]));
                }
        }
        __syncthreads();
    }

    int g = lane >> 2, tg = lane & 3;
#pragma unroll
    for (int mi = 0; mi < 2; mi++) {
#pragma unroll
        for (int nj = 0; nj < 8; nj++) {
            int col = n0 + wn + nj * 8 + tg * 2;
#pragma unroll
            for (int half = 0; half < 2; half++) {
                long row = m0 + wm + mi * 16 + g + half * 8;
                float v0 = acc[mi][nj][half * 2];
                float v1 = acc[mi][nj][half * 2 + 1];
                if (EPI == 0 || EPI == 1) {
                    if (EPI == 1) { v0 += bias[col]; v1 += bias[col + 1]; }
                    *(unsigned*)((__nv_bfloat16*)Yv + row * Ntot + col) = pack_bf(v0, v1);
                } else if (EPI == 2) {
                    int bb = (int)(row >> 16), p = (int)(row & 65535);
                    float r0 = R[((long)(bb * 128 + col)) * NPIX + p];
                    float r1 = R[((long)(bb * 128 + col + 1)) * NPIX + p];
                    float2 o = make_float2(r0 + S[col] * v0, r1 + S[col + 1] * v1);
                    *(float2*)((float*)Yv + row * 128 + col) = o;
                } else {  // EPI 3
                    int bb = (int)(row >> 16), p = (int)(row & 65535);
                    float2 rr = *(const float2*)&R[row * 128 + col];
                    ((float*)Yv)[((long)(bb * 128 + col)) * NPIX + p]     = rr.x + S[col] * v0;
                    ((float*)Yv)[((long)(bb * 128 + col + 1)) * NPIX + p] = rr.y + S[col + 1] * v1;
                }
            }
        }
    }
}

// ---------------------------------------------------------------------------
// Depthwise 3x3 NHWC bf16, SAME padding. Tile 8x32 px, 16 channels per block.
// Channel-pair slabs (conflict-free compute LDS): in_s[h][cg][row*36+col].
// R10 staging: 4-px items, register transpose, one STS.128 per slab
// ({px0..px3}), 16B-aligned (po = ry*36 + ri*4).
// GATE: two channel halves, writes their product (FFN gate).
// ---------------------------------------------------------------------------
template <int C, bool GATE>
__global__ __launch_bounds__(256) void dw_k(const __nv_bfloat16* __restrict__ X,
                                            const float* __restrict__ Wd,
                                            __nv_bfloat16* __restrict__ Y)
{
    constexpr int NH = GATE ? 2 : 1;
    __shared__ unsigned in_s[NH][8][364];   // 8 slabs x (10 rows * 36 + pad)
    __shared__ float w_s[NH][9][16];

    int t = threadIdx.x;
    int bx = blockIdx.x;
    int ty = bx >> 3, tx = bx & 7;
    int c0 = blockIdx.y * 16;
    long ibase = (long)blockIdx.z * NPIX;

    for (int i = t; i < NH * 144; i += 256) {
        int h = i / 144, j = i % 144, ch = j / 9, tap = j % 9;
        w_s[h][tap][ch] = Wd[(c0 + h * 128 + ch) * 9 + tap];
    }
    // stage 10x34 halo as 4-px items: 90 items, register transpose, STS.128
    for (int lin = t; lin < 90; lin += 256) {
        int ry = lin / 9, ri = lin % 9;
        int rx0 = ri * 4;
        int yy = ty * 8 + ry - 1;
        bool oky = (yy >= 0 && yy < 256);
        int po = ry * 36 + rx0;
#pragma unroll
        for (int h = 0; h < NH; h++) {
            unsigned vv[4][8];
#pragma unroll
            for (int p = 0; p < 4; p++) {
                int xx = tx * 32 + rx0 + p - 1;
                uint4 v0 = make_uint4(0,0,0,0), v1 = make_uint4(0,0,0,0);
                if (oky && xx >= 0 && xx < 256 && rx0 + p < 34) {
                    const uint4* s = (const uint4*)(X + (ibase + yy * 256 + xx) * C + c0 + h * 128);
                    v0 = s[0]; v1 = s[1];
                }
                *(uint4*)&vv[p][0] = v0;
                *(uint4*)&vv[p][4] = v1;
            }
#pragma unroll
            for (int s = 0; s < 8; s++) {
                uint4 w = make_uint4(vv[0][s], vv[1][s], vv[2][s], vv[3][s]);
                *(uint4*)&in_s[h][s][po] = w;
            }
        }
    }
    __syncthreads();

    int oy = t >> 5;            // 0..7 output row
    int xg = (t >> 3) & 3;      // 0..3 x-group (8 px each)
    int cg = t & 7;             // 0..7 channel pair
    int ox0 = xg * 8;

    float2 acc[NH][8];
#pragma unroll
    for (int h = 0; h < NH; h++)
#pragma unroll
        for (int j = 0; j < 8; j++) acc[h][j] = make_float2(0.f, 0.f);

#pragma unroll
    for (int h = 0; h < NH; h++) {
        float2 wr[9];
#pragma unroll
        for (int tap = 0; tap < 9; tap++)
            wr[tap] = make_float2(w_s[h][tap][cg * 2], w_s[h][tap][cg * 2 + 1]);

#pragma unroll
        for (int ky = 0; ky < 3; ky++) {
            const unsigned* rp = &in_s[h][cg][(oy + ky) * 36 + ox0];
            uint4 va_ = *(const uint4*)rp;
            uint4 vb_ = *(const uint4*)(rp + 4);
            uint2 vc_ = *(const uint2*)(rp + 8);
            float2 f[10];
            f[0] = unpack_bf(va_.x); f[1] = unpack_bf(va_.y);
            f[2] = unpack_bf(va_.z); f[3] = unpack_bf(va_.w);
            f[4] = unpack_bf(vb_.x); f[5] = unpack_bf(vb_.y);
            f[6] = unpack_bf(vb_.z); f[7] = unpack_bf(vb_.w);
            f[8] = unpack_bf(vc_.x); f[9] = unpack_bf(vc_.y);
#pragma unroll
            for (int kx = 0; kx < 3; kx++) {
                float2 w = wr[ky * 3 + kx];
#pragma unroll
                for (int j = 0; j < 8; j++) {
                    acc[h][j].x += f[j + kx].x * w.x;
                    acc[h][j].y += f[j + kx].y * w.y;
                }
            }
        }
    }

    long opix = ibase + (ty * 8 + oy) * 256 + tx * 32 + ox0;
    if (!GATE) {
#pragma unroll
        for (int j = 0; j < 8; j++)
            *(unsigned*)(Y + (opix + j) * C + c0 + cg * 2) =
                pack_bf(acc[0][j].x, acc[0][j].y);
    } else {
#pragma unroll
        for (int j = 0; j < 8; j++)
            *(unsigned*)(Y + (opix + j) * 128 + c0 + cg * 2) =
                pack_bf(acc[0][j].x * acc[1][j].x, acc[0][j].y * acc[1][j].y);
    }
}

// ---------------------------------------------------------------------------
// Patch attention (8x8 circular conv of q,k) fused with LN2 and * v.
// R10: inner product in packed fma.rn.f32x2 (2 channels per FMA instr,
// bitwise-identical fp32 rounding).
// ---------------------------------------------------------------------------
__global__ __launch_bounds__(256) void attn_k(const __nv_bfloat16* __restrict__ qkv,
                                              const float* __restrict__ g2,
                                              const float* __restrict__ b2,
                                              __nv_bfloat16* __restrict__ va)
{
    extern __shared__ char smdyn[];
    unsigned* q_s = (unsigned*)smdyn;        // [64*128]
    unsigned* k_s = q_s + 64 * 128;          // [64*128]
    float* attn = (float*)smdyn;             // [64*257] alias
    __shared__ float red[64][4][2];

    int t = threadIdx.x;
    int bx = blockIdx.x;
    int py = bx >> 5, px = bx & 31;
    long ibase = (long)blockIdx.z * NPIX;

    for (int r = 0; r < 8; r++) {
        int lin = r * 256 + t;
        int pix = lin >> 5, c4 = lin & 31;
        long gpix = ibase + (py * 8 + (pix >> 3)) * 256 + px * 8 + (pix & 7);
        ((uint4*)q_s)[pix * 32 + c4] = __ldg((const uint4*)(qkv + gpix * 768) + c4);
        ((uint4*)k_s)[pix * 32 + c4] = __ldg((const uint4*)(qkv + gpix * 768 + 256) + c4);
    }
    __syncthreads();

    int cp = t & 127;
    int mg = t >> 7;
    u64 acc[4][8];
#pragma unroll
    for (int a = 0; a < 4; a++)
#pragma unroll
        for (int b = 0; b < 8; b++) acc[a][b] = 0ULL;

#pragma unroll
    for (int i = 0; i < 8; i++) {
        u64 qv[8];
#pragma unroll
        for (int jx = 0; jx < 8; jx++)
            qv[jx] = bf2_to_f32x2(q_s[(i * 8 + jx) * 128 + cp]);
#pragma unroll
        for (int mi = 0; mi < 4; mi++) {
            int m = mg + 2 * mi;
            int kr = (m - i) & 7;
            u64 kv[8];
#pragma unroll
            for (int j = 0; j < 8; j++)
                kv[j] = bf2_to_f32x2(k_s[(kr * 8 + j) * 128 + cp]);
#pragma unroll
            for (int jo = 0; jo < 8; jo++)
#pragma unroll
                for (int jx = 0; jx < 8; jx++)
                    FMA_F32X2(acc[mi][jo], qv[jx], kv[(jo - jx) & 7]);
        }
    }
    __syncthreads();

#pragma unroll
    for (int mi = 0; mi < 4; mi++) {
        int m = mg + 2 * mi;
#pragma unroll
        for (int jo = 0; jo < 8; jo++) {
            float lo, hi;
            asm("mov.b64 {%0,%1}, %2;" : "=f"(lo), "=f"(hi) : "l"(acc[mi][jo]));
            attn[(m * 8 + jo) * 257 + 2 * cp]     = lo;
            attn[(m * 8 + jo) * 257 + 2 * cp + 1] = hi;
        }
    }
    __syncthreads();

    int pix = t >> 2, q4 = t & 3;
    const float* ap = attn + pix * 257 + q4 * 64;
    float s = 0.f, s2 = 0.f;
#pragma unroll
    for (int i = 0; i < 64; i++) { float v = ap[i]; s += v; s2 += v * v; }
    red[pix][q4][0] = s; red[pix][q4][1] = s2;
    __syncthreads();
    s  = red[pix][0][0] + red[pix][1][0] + red[pix][2][0] + red[pix][3][0];
    s2 = red[pix][0][1] + red[pix][1][1] + red[pix][2][1] + red[pix][3][1];
    float m = s * (1.f / 256.f);
    float r = rsqrtf(s2 * (1.f / 256.f) - m * m + 1e-6f);

    long gpix = ibase + (py * 8 + (pix >> 3)) * 256 + px * 8 + (pix & 7);
    const __nv_bfloat16* vp = qkv + gpix * 768 + 512 + q4 * 64;
    __nv_bfloat16* op = va + gpix * 256 + q4 * 64;
#pragma unroll
    for (int i = 0; i < 64; i += 2) {
        int c = q4 * 64 + i;
        float a0 = (ap[i] - m) * r * __ldg(g2 + c) + __ldg(b2 + c);
        float a1 = (ap[i + 1] - m) * r * __ldg(g2 + c + 1) + __ldg(b2 + c + 1);
        float2 v = unpack_bf(*(const unsigned*)(vp + i));
        *(unsigned*)(op + i) = pack_bf(a0 * v.x, a1 * v.y);
    }
}

// ---------------------------------------------------------------------------

extern "C" void kernel_launch(void* const* d_in, const int* in_sizes, int n_in,
                              void* d_out, int out_size)
{
    const float* x     = (const float*)d_in[0];
    const float* n1w   = (const float*)d_in[1];
    const float* n1b   = (const float*)d_in[2];
    const float* w_h1  = (const float*)d_in[3];
    const float* w_dw1 = (const float*)d_in[4];
    const float* n2w   = (const float*)d_in[5];
    const float* n2b   = (const float*)d_in[6];
    const float* w_p1  = (const float*)d_in[7];
    const float* n3w   = (const float*)d_in[8];
    const float* n3b   = (const float*)d_in[9];
    const float* w_h2  = (const float*)d_in[10];
    const float* b_h2  = (const float*)d_in[11];
    const float* w_dw2 = (const float*)d_in[12];
    const float* w_p2  = (const float*)d_in[13];
    const float* sc1   = (const float*)d_in[14];
    const float* sc2   = (const float*)d_in[15];
    float* out = (float*)d_out;

    __nv_bfloat16 *hn, *buf1, *buf2, *wb;
    cudaGetSymbolAddress((void**)&hn,   g_hn);
    cudaGetSymbolAddress((void**)&buf1, g_buf1);
    cudaGetSymbolAddress((void**)&buf2, g_buf2);
    cudaGetSymbolAddress((void**)&wb,   g_wb);
    float* x1f = (float*)buf2;

    const int GSM = 73728;
    cudaFuncSetAttribute(attn_k, cudaFuncAttributeMaxDynamicSharedMemorySize, 65792);
    cudaFuncSetAttribute(gemm_tc<128, 0>, cudaFuncAttributeMaxDynamicSharedMemorySize, GSM);
    cudaFuncSetAttribute(gemm_tc<256, 2>, cudaFuncAttributeMaxDynamicSharedMemorySize, GSM);
    cudaFuncSetAttribute(gemm_tc<128, 1>, cudaFuncAttributeMaxDynamicSharedMemorySize, GSM);
    cudaFuncSetAttribute(gemm_tc<128, 3>, cudaFuncAttributeMaxDynamicSharedMemorySize, GSM);

    // weights -> bf16
    wcvt_k<<<704, 256>>>(w_h1, w_p1, w_h2, w_p2, wb);

    // 1. LN1: x NCHW -> hn NHWC bf16
    ln1_k<<<512, 256>>>(x, n1w, n1b, hn);

    // 2. hidden = hn @ w_h1^T  -> buf1 [M,768] bf16
    gemm_tc<128, 0><<<dim3(1024, 6), 256, GSM>>>(hn, wb, nullptr, nullptr, nullptr, buf1, 768);

    // 3. qkv = dw3x3(hidden) -> buf2 [M,768] bf16
    dw_k<768, false><<<dim3(256, 48, 2), 256>>>(buf1, w_dw1, buf2);

    // 4. va = v * LN2(patchconv(q,k)) -> buf1 [M,256] bf16
    attn_k<<<dim3(1024, 1, 2), 256, 65792>>>(buf2, n2w, n2b, buf1);

    // 5. x1 = x + scale1 * (va @ w_p1^T) -> buf2 as fp32 NHWC [M,128]
    gemm_tc<256, 2><<<dim3(1024, 1), 256, GSM>>>(buf1, wb + 98304, nullptr, x, sc1, x1f, 128);

    // 6. LN3: x1 -> hn bf16 NHWC
    ln3_k<<<16384, 256>>>(x1f, n3w, n3b, hn);

    // 7. g = hn @ w_h2^T + b_h2 -> buf1 [M,256] bf16
    gemm_tc<128, 1><<<dim3(1024, 2), 256, GSM>>>(hn, wb + 131072, b_h2, nullptr, nullptr, buf1, 256);

    // 8. mgate = dw(g)[0:128] * dw(g)[128:256] -> hn [M,128] bf16
    dw_k<256, true><<<dim3(256, 8, 2), 256>>>(buf1, w_dw2, hn);

    // 9. out = x1 + scale2 * (mgate @ w_p2^T) -> d_out NCHW fp32
    gemm_tc<128, 3><<<dim3(1024, 1), 256, GSM>>>(hn, wb + 163840, nullptr, x1f, sc2, out, 128);
}

// round 13
// speedup vs baseline: 1.0030x; 1.0030x over previous
#include <cuda_runtime.h>
#include <cuda_bf16.h>
#include <cstdint>

// ===========================================================================
// NHWC bf16 pipeline with tensor-core (mma.sync bf16) GEMMs.
// R10: dw_k staging via 4-px register transpose + STS.128 (wavefront cut);
//      attn_k inner product in packed fma.rn.f32x2 (FMA instr halved).
// ===========================================================================

#define NPIX 65536           // per image
#define MTOT 131072L         // total pixels (batch 2)

typedef unsigned long long u64;

__device__ __align__(16) __nv_bfloat16 g_hn[MTOT * 128];    // LN outs / mgate
__device__ __align__(16) __nv_bfloat16 g_buf1[MTOT * 768];  // hidden / va / g
__device__ __align__(16) __nv_bfloat16 g_buf2[MTOT * 768];  // qkv / x1(fp32)
__device__ __align__(16) __nv_bfloat16 g_wb[180224];        // bf16 weights

__device__ __forceinline__ unsigned pack_bf(float a, float b) {
    __nv_bfloat162 h = __float22bfloat162_rn(make_float2(a, b));
    return *(unsigned*)&h;
}
__device__ __forceinline__ float2 unpack_bf(unsigned u) {
    __nv_bfloat162 h = *(__nv_bfloat162*)&u;
    return make_float2(__bfloat162float(h.x), __bfloat162float(h.y));
}
__device__ __forceinline__ uint32_t smem_u32(const void* p) {
    return (uint32_t)__cvta_generic_to_shared(p);
}
__device__ __forceinline__ void cp16(void* dst, const void* src) {
    asm volatile("cp.async.cg.shared.global [%0], [%1], 16;"
                 :: "r"(smem_u32(dst)), "l"(src));
}
// bf16x2 -> packed f32x2 (bf16 widens by <<16; no cvt needed)
__device__ __forceinline__ u64 bf2_to_f32x2(unsigned u) {
    unsigned lo = u << 16, hi = u & 0xffff0000u;
    u64 d;
    asm("mov.b64 %0, {%1,%2};" : "=l"(d) : "r"(lo), "r"(hi));
    return d;
}
#define FMA_F32X2(d, a, b) \
    asm("fma.rn.f32x2 %0, %1, %2, %0;" : "+l"(d) : "l"(a), "l"(b))

// ---------------------------------------------------------------------------
// Weight conversion fp32 -> bf16 (once per launch; tiny)
// ---------------------------------------------------------------------------
__global__ void wcvt_k(const float* __restrict__ w1, const float* __restrict__ w2,
                       const float* __restrict__ w3, const float* __restrict__ w4,
                       __nv_bfloat16* __restrict__ o)
{
    int i = blockIdx.x * 256 + threadIdx.x;
    if (i < 98304)       o[i] = __float2bfloat16(w1[i]);
    else if (i < 131072) o[i] = __float2bfloat16(w2[i - 98304]);
    else if (i < 163840) o[i] = __float2bfloat16(w3[i - 131072]);
    else if (i < 180224) o[i] = __float2bfloat16(w4[i - 163840]);
}

// ---------------------------------------------------------------------------
// LN1: x NCHW fp32 -> y NHWC bf16 (C=128).
// ---------------------------------------------------------------------------
__global__ __launch_bounds__(256) void ln1_k(const float* __restrict__ x,
                                             const float* __restrict__ g,
                                             const float* __restrict__ b,
                                             __nv_bfloat16* __restrict__ y)
{
    __shared__ __nv_bfloat16 st[256 * 18];
    int t = threadIdx.x;
    long gp0 = (long)blockIdx.x * 256;
    long gp = gp0 + t;
    int bb = (int)(gp >> 16);
    int p  = (int)(gp & 65535);
    const float* xp = x + (long)bb * 128 * NPIX + p;

    float s = 0.f, s2 = 0.f;
    for (int c = 0; c < 128; c++) {
        float v = xp[(long)c * NPIX];
        s += v; s2 += v * v;
    }
    float m = s * (1.f / 128.f);
    float r = rsqrtf(s2 * (1.f / 128.f) - m * m + 1e-6f);

    for (int c0 = 0; c0 < 128; c0 += 16) {
#pragma unroll
        for (int cc = 0; cc < 16; cc++) {
            float v = xp[(long)(c0 + cc) * NPIX];
            st[t * 18 + cc] = __float2bfloat16((v - m) * r * g[c0 + cc] + b[c0 + cc]);
        }
        __syncthreads();
        for (int it = 0; it < 8; it++) {
            int lin = it * 256 + t;
            int pl = lin >> 3, cw = lin & 7;
            unsigned v = *(unsigned*)&st[pl * 18 + cw * 2];
            *(unsigned*)(y + (gp0 + pl) * 128 + c0 + cw * 2) = v;
        }
        __syncthreads();
    }
}

// ---------------------------------------------------------------------------
// LN3: x1 NHWC fp32 -> y NHWC bf16 (C=128). Warp per pixel.
// ---------------------------------------------------------------------------
__global__ __launch_bounds__(256) void ln3_k(const float* __restrict__ x,
                                             const float* __restrict__ g,
                                             const float* __restrict__ b,
                                             __nv_bfloat16* __restrict__ y)
{
    int t = threadIdx.x, lane = t & 31, w = t >> 5;
    long p = (long)blockIdx.x * 8 + w;
    float4 v = *(const float4*)&x[p * 128 + lane * 4];
    float s = v.x + v.y + v.z + v.w;
    float s2 = v.x * v.x + v.y * v.y + v.z * v.z + v.w * v.w;
#pragma unroll
    for (int o = 16; o; o >>= 1) {
        s  += __shfl_xor_sync(0xffffffffu, s, o);
        s2 += __shfl_xor_sync(0xffffffffu, s2, o);
    }
    float m = s * (1.f / 128.f);
    float r = rsqrtf(s2 * (1.f / 128.f) - m * m + 1e-6f);
    int c = lane * 4;
    float o0 = (v.x - m) * r * g[c]     + b[c];
    float o1 = (v.y - m) * r * g[c + 1] + b[c + 1];
    float o2 = (v.z - m) * r * g[c + 2] + b[c + 2];
    float o3 = (v.w - m) * r * g[c + 3] + b[c + 3];
    uint2 u = make_uint2(pack_bf(o0, o1), pack_bf(o2, o3));
    *(uint2*)(y + p * 128 + c) = u;
}

// ---------------------------------------------------------------------------
// Tensor-core GEMM with cp.async 2-stage double buffering.
//   A: NHWC bf16 activations [M, K], B: bf16 weights [Ntot, K]
// EPI 0: bf16 out | 1: bf16 out + bias | 2: fp32 NHWC = x_nchw + S*acc |
// EPI 3: fp32 NCHW = x1_nhwc + S*acc.
// Block tile 128x128x64, 8 warps. Dynamic smem 73728 B.
// ---------------------------------------------------------------------------
template <int K, int EPI>
__global__ __launch_bounds__(256) void gemm_tc(
    const __nv_bfloat16* __restrict__ A, const __nv_bfloat16* __restrict__ B,
    const float* __restrict__ bias, const float* __restrict__ R,
    const float* __restrict__ S, void* __restrict__ Yv, int Ntot)
{
    constexpr int LDS_ = 72;
    constexpr int MATSZ = 128 * LDS_;        // 9216 elems
    constexpr int STAGE = 2 * MATSZ;         // A+B per stage
    extern __shared__ __nv_bfloat16 sm[];

    int t = threadIdx.x;
    long m0 = (long)blockIdx.x * 128;
    int n0 = blockIdx.y * 128;
    int wid = t >> 5, lane = t & 31;
    int wm = (wid & 3) * 32, wn = (wid >> 2) * 64;

    float acc[2][8][4];
#pragma unroll
    for (int i = 0; i < 2; i++)
#pragma unroll
        for (int j = 0; j < 8; j++)
#pragma unroll
            for (int q = 0; q < 4; q++) acc[i][j][q] = 0.f;

    int lrow = t >> 3, lcol = (t & 7) * 8;

    auto load_stage = [&](int k0, int s) {
        __nv_bfloat16* As_ = sm + s * STAGE;
        __nv_bfloat16* Bs_ = As_ + MATSZ;
#pragma unroll
        for (int pp = 0; pp < 4; pp++) {
            int row = pp * 32 + lrow;
            cp16(&As_[row * LDS_ + lcol], &A[(m0 + row) * K + k0 + lcol]);
            cp16(&Bs_[row * LDS_ + lcol], &B[(long)(n0 + row) * K + k0 + lcol]);
        }
        asm volatile("cp.async.commit_group;");
    };

    constexpr int NSTEP = K / 64;
    load_stage(0, 0);

#pragma unroll
    for (int st = 0; st < NSTEP; st++) {
        if (st + 1 < NSTEP) {
            load_stage((st + 1) * 64, (st + 1) & 1);
            asm volatile("cp.async.wait_group 1;");
        } else {
            asm volatile("cp.async.wait_group 0;");
        }
        __syncthreads();

        const __nv_bfloat16* As_ = sm + (st & 1) * STAGE;
        const __nv_bfloat16* Bs_ = As_ + MATSZ;

#pragma unroll
        for (int kk = 0; kk < 4; kk++) {
            uint32_t a[2][4], bf[8][2];
#pragma unroll
            for (int mi = 0; mi < 2; mi++) {
                uint32_t addr = smem_u32(
                    &As_[(wm + mi * 16 + (lane & 15)) * LDS_ + kk * 16 + (lane >> 4) * 8]);
                asm volatile("ldmatrix.sync.aligned.m8n8.x4.shared.b16 {%0,%1,%2,%3}, [%4];"
                             : "=r"(a[mi][0]), "=r"(a[mi][1]), "=r"(a[mi][2]), "=r"(a[mi][3])
                             : "r"(addr));
            }
#pragma unroll
            for (int nb = 0; nb < 4; nb++) {
                int row = wn + nb * 16 + ((lane >> 4) << 3) + (lane & 7);
                int col = kk * 16 + ((lane >> 3) & 1) * 8;
                uint32_t addr = smem_u32(&Bs_[row * LDS_ + col]);
                uint32_t r0, r1, r2, r3;
                asm volatile("ldmatrix.sync.aligned.m8n8.x4.shared.b16 {%0,%1,%2,%3}, [%4];"
                             : "=r"(r0), "=r"(r1), "=r"(r2), "=r"(r3) : "r"(addr));
                bf[nb * 2][0] = r0;     bf[nb * 2][1] = r1;
                bf[nb * 2 + 1][0] = r2; bf[nb * 2 + 1][1] = r3;
            }
#pragma unroll
            for (int mi = 0; mi < 2; mi++)
#pragma unroll
                for (int nj = 0; nj < 8; nj++) {
                    asm volatile(
                        "mma.sync.aligned.m16n8k16.row.col.f32.bf16.bf16.f32 "
                        "{%0,%1,%2,%3}, {%4,%5,%6,%7}, {%8,%9}, {%0,%1,%2,%3};"
                        : "+f"(acc[mi][nj][0]), "+f"(acc[mi][nj][1]),
                          "+f"(acc[mi][nj][2]), "+f"(acc[mi][nj][3])
                        : "r"(a[mi][0]), "r"(a[mi][1]), "r"(a[mi][2]), "r"(a[mi][3]),
                          "r"(bf[nj][0]), "r"(bf[nj][1]));
                }
        }
        __syncthreads();
    }

    int g = lane >> 2, tg = lane & 3;
#pragma unroll
    for (int mi = 0; mi < 2; mi++) {
#pragma unroll
        for (int nj = 0; nj < 8; nj++) {
            int col = n0 + wn + nj * 8 + tg * 2;
#pragma unroll
            for (int half = 0; half < 2; half++) {
                long row = m0 + wm + mi * 16 + g + half * 8;
                float v0 = acc[mi][nj][half * 2];
                float v1 = acc[mi][nj][half * 2 + 1];
                if (EPI == 0 || EPI == 1) {
                    if (EPI == 1) { v0 += bias[col]; v1 += bias[col + 1]; }
                    *(unsigned*)((__nv_bfloat16*)Yv + row * Ntot + col) = pack_bf(v0, v1);
                } else if (EPI == 2) {
                    int bb = (int)(row >> 16), p = (int)(row & 65535);
                    float r0 = R[((long)(bb * 128 + col)) * NPIX + p];
                    float r1 = R[((long)(bb * 128 + col + 1)) * NPIX + p];
                    float2 o = make_float2(r0 + S[col] * v0, r1 + S[col + 1] * v1);
                    *(float2*)((float*)Yv + row * 128 + col) = o;
                } else {  // EPI 3
                    int bb = (int)(row >> 16), p = (int)(row & 65535);
                    float2 rr = *(const float2*)&R[row * 128 + col];
                    ((float*)Yv)[((long)(bb * 128 + col)) * NPIX + p]     = rr.x + S[col] * v0;
                    ((float*)Yv)[((long)(bb * 128 + col + 1)) * NPIX + p] = rr.y + S[col + 1] * v1;
                }
            }
        }
    }
}

// ---------------------------------------------------------------------------
// Depthwise 3x3 NHWC bf16, SAME padding. Tile 8x32 px, 16 channels per block.
// Channel-pair slabs (conflict-free compute LDS): in_s[h][cg][row*36+col].
// R10 staging: 4-px items, register transpose, one STS.128 per slab
// ({px0..px3}), 16B-aligned (po = ry*36 + ri*4).
// GATE: two channel halves, writes their product (FFN gate).
// ---------------------------------------------------------------------------
template <int C, bool GATE>
__global__ __launch_bounds__(256) void dw_k(const __nv_bfloat16* __restrict__ X,
                                            const float* __restrict__ Wd,
                                            __nv_bfloat16* __restrict__ Y)
{
    constexpr int NH = GATE ? 2 : 1;
    __shared__ unsigned in_s[NH][8][364];   // 8 slabs x (10 rows * 36 + pad)
    __shared__ float w_s[NH][9][16];

    int t = threadIdx.x;
    int bx = blockIdx.x;
    int ty = bx >> 3, tx = bx & 7;
    int c0 = blockIdx.y * 16;
    long ibase = (long)blockIdx.z * NPIX;

    for (int i = t; i < NH * 144; i += 256) {
        int h = i / 144, j = i % 144, ch = j / 9, tap = j % 9;
        w_s[h][tap][ch] = Wd[(c0 + h * 128 + ch) * 9 + tap];
    }
    // stage 10x34 halo as 4-px items: 90 items, register transpose, STS.128
    for (int lin = t; lin < 90; lin += 256) {
        int ry = lin / 9, ri = lin % 9;
        int rx0 = ri * 4;
        int yy = ty * 8 + ry - 1;
        bool oky = (yy >= 0 && yy < 256);
        int po = ry * 36 + rx0;
#pragma unroll
        for (int h = 0; h < NH; h++) {
            unsigned vv[4][8];
#pragma unroll
            for (int p = 0; p < 4; p++) {
                int xx = tx * 32 + rx0 + p - 1;
                uint4 v0 = make_uint4(0,0,0,0), v1 = make_uint4(0,0,0,0);
                if (oky && xx >= 0 && xx < 256 && rx0 + p < 34) {
                    const uint4* s = (const uint4*)(X + (ibase + yy * 256 + xx) * C + c0 + h * 128);
                    v0 = s[0]; v1 = s[1];
                }
                *(uint4*)&vv[p][0] = v0;
                *(uint4*)&vv[p][4] = v1;
            }
#pragma unroll
            for (int s = 0; s < 8; s++) {
                uint4 w = make_uint4(vv[0][s], vv[1][s], vv[2][s], vv[3][s]);
                *(uint4*)&in_s[h][s][po] = w;
            }
        }
    }
    __syncthreads();

    int oy = t >> 5;            // 0..7 output row
    int xg = (t >> 3) & 3;      // 0..3 x-group (8 px each)
    int cg = t & 7;             // 0..7 channel pair
    int ox0 = xg * 8;

    float2 acc[NH][8];
#pragma unroll
    for (int h = 0; h < NH; h++)
#pragma unroll
        for (int j = 0; j < 8; j++) acc[h][j] = make_float2(0.f, 0.f);

#pragma unroll
    for (int h = 0; h < NH; h++) {
        float2 wr[9];
#pragma unroll
        for (int tap = 0; tap < 9; tap++)
            wr[tap] = make_float2(w_s[h][tap][cg * 2], w_s[h][tap][cg * 2 + 1]);

#pragma unroll
        for (int ky = 0; ky < 3; ky++) {
            const unsigned* rp = &in_s[h][cg][(oy + ky) * 36 + ox0];
            uint4 va_ = *(const uint4*)rp;
            uint4 vb_ = *(const uint4*)(rp + 4);
            uint2 vc_ = *(const uint2*)(rp + 8);
            float2 f[10];
            f[0] = unpack_bf(va_.x); f[1] = unpack_bf(va_.y);
            f[2] = unpack_bf(va_.z); f[3] = unpack_bf(va_.w);
            f[4] = unpack_bf(vb_.x); f[5] = unpack_bf(vb_.y);
            f[6] = unpack_bf(vb_.z); f[7] = unpack_bf(vb_.w);
            f[8] = unpack_bf(vc_.x); f[9] = unpack_bf(vc_.y);
#pragma unroll
            for (int kx = 0; kx < 3; kx++) {
                float2 w = wr[ky * 3 + kx];
#pragma unroll
                for (int j = 0; j < 8; j++) {
                    acc[h][j].x += f[j + kx].x * w.x;
                    acc[h][j].y += f[j + kx].y * w.y;
                }
            }
        }
    }

    long opix = ibase + (ty * 8 + oy) * 256 + tx * 32 + ox0;
    if (!GATE) {
#pragma unroll
        for (int j = 0; j < 8; j++)
            *(unsigned*)(Y + (opix + j) * C + c0 + cg * 2) =
                pack_bf(acc[0][j].x, acc[0][j].y);
    } else {
#pragma unroll
        for (int j = 0; j < 8; j++)
            *(unsigned*)(Y + (opix + j) * 128 + c0 + cg * 2) =
                pack_bf(acc[0][j].x * acc[1][j].x, acc[0][j].y * acc[1][j].y);
    }
}

// ---------------------------------------------------------------------------
// Patch attention (8x8 circular conv of q,k) fused with LN2 and * v.
// R10: inner product in packed fma.rn.f32x2 (2 channels per FMA instr,
// bitwise-identical fp32 rounding).
// ---------------------------------------------------------------------------
__global__ __launch_bounds__(256) void attn_k(const __nv_bfloat16* __restrict__ qkv,
                                              const float* __restrict__ g2,
                                              const float* __restrict__ b2,
                                              __nv_bfloat16* __restrict__ va)
{
    extern __shared__ char smdyn[];
    unsigned* q_s = (unsigned*)smdyn;        // [64*128]
    unsigned* k_s = q_s + 64 * 128;          // [64*128]
    float* attn = (float*)smdyn;             // [64*257] alias
    __shared__ float red[64][4][2];

    int t = threadIdx.x;
    int bx = blockIdx.x;
    int py = bx >> 5, px = bx & 31;
    long ibase = (long)blockIdx.z * NPIX;

    for (int r = 0; r < 8; r++) {
        int lin = r * 256 + t;
        int pix = lin >> 5, c4 = lin & 31;
        long gpix = ibase + (py * 8 + (pix >> 3)) * 256 + px * 8 + (pix & 7);
        ((uint4*)q_s)[pix * 32 + c4] = __ldg((const uint4*)(qkv + gpix * 768) + c4);
        ((uint4*)k_s)[pix * 32 + c4] = __ldg((const uint4*)(qkv + gpix * 768 + 256) + c4);
    }
    __syncthreads();

    int cp = t & 127;
    int mg = t >> 7;
    u64 acc[4][8];
#pragma unroll
    for (int a = 0; a < 4; a++)
#pragma unroll
        for (int b = 0; b < 8; b++) acc[a][b] = 0ULL;

#pragma unroll
    for (int i = 0; i < 8; i++) {
        u64 qv[8];
#pragma unroll
        for (int jx = 0; jx < 8; jx++)
            qv[jx] = bf2_to_f32x2(q_s[(i * 8 + jx) * 128 + cp]);
#pragma unroll
        for (int mi = 0; mi < 4; mi++) {
            int m = mg + 2 * mi;
            int kr = (m - i) & 7;
            u64 kv[8];
#pragma unroll
            for (int j = 0; j < 8; j++)
                kv[j] = bf2_to_f32x2(k_s[(kr * 8 + j) * 128 + cp]);
#pragma unroll
            for (int jo = 0; jo < 8; jo++)
#pragma unroll
                for (int jx = 0; jx < 8; jx++)
                    FMA_F32X2(acc[mi][jo], qv[jx], kv[(jo - jx) & 7]);
        }
    }
    __syncthreads();

#pragma unroll
    for (int mi = 0; mi < 4; mi++) {
        int m = mg + 2 * mi;
#pragma unroll
        for (int jo = 0; jo < 8; jo++) {
            float lo, hi;
            asm("mov.b64 {%0,%1}, %2;" : "=f"(lo), "=f"(hi) : "l"(acc[mi][jo]));
            attn[(m * 8 + jo) * 257 + 2 * cp]     = lo;
            attn[(m * 8 + jo) * 257 + 2 * cp + 1] = hi;
        }
    }
    __syncthreads();

    int pix = t >> 2, q4 = t & 3;
    const float* ap = attn + pix * 257 + q4 * 64;
    float s = 0.f, s2 = 0.f;
#pragma unroll
    for (int i = 0; i < 64; i++) { float v = ap[i]; s += v; s2 += v * v; }
    red[pix][q4][0] = s; red[pix][q4][1] = s2;
    __syncthreads();
    s  = red[pix][0][0] + red[pix][1][0] + red[pix][2][0] + red[pix][3][0];
    s2 = red[pix][0][1] + red[pix][1][1] + red[pix][2][1] + red[pix][3][1];
    float m = s * (1.f / 256.f);
    float r = rsqrtf(s2 * (1.f / 256.f) - m * m + 1e-6f);

    long gpix = ibase + (py * 8 + (pix >> 3)) * 256 + px * 8 + (pix & 7);
    const __nv_bfloat16* vp = qkv + gpix * 768 + 512 + q4 * 64;
    __nv_bfloat16* op = va + gpix * 256 + q4 * 64;
#pragma unroll
    for (int i = 0; i < 64; i += 2) {
        int c = q4 * 64 + i;
        float a0 = (ap[i] - m) * r * __ldg(g2 + c) + __ldg(b2 + c);
        float a1 = (ap[i + 1] - m) * r * __ldg(g2 + c + 1) + __ldg(b2 + c + 1);
        float2 v = unpack_bf(*(const unsigned*)(vp + i));
        *(unsigned*)(op + i) = pack_bf(a0 * v.x, a1 * v.y);
    }
}

// ---------------------------------------------------------------------------

extern "C" void kernel_launch(void* const* d_in, const int* in_sizes, int n_in,
                              void* d_out, int out_size)
{
    const float* x     = (const float*)d_in[0];
    const float* n1w   = (const float*)d_in[1];
    const float* n1b   = (const float*)d_in[2];
    const float* w_h1  = (const float*)d_in[3];
    const float* w_dw1 = (const float*)d_in[4];
    const float* n2w   = (const float*)d_in[5];
    const float* n2b   = (const float*)d_in[6];
    const float* w_p1  = (const float*)d_in[7];
    const float* n3w   = (const float*)d_in[8];
    const float* n3b   = (const float*)d_in[9];
    const float* w_h2  = (const float*)d_in[10];
    const float* b_h2  = (const float*)d_in[11];
    const float* w_dw2 = (const float*)d_in[12];
    const float* w_p2  = (const float*)d_in[13];
    const float* sc1   = (const float*)d_in[14];
    const float* sc2   = (const float*)d_in[15];
    float* out = (float*)d_out;

    __nv_bfloat16 *hn, *buf1, *buf2, *wb;
    cudaGetSymbolAddress((void**)&hn,   g_hn);
    cudaGetSymbolAddress((void**)&buf1, g_buf1);
    cudaGetSymbolAddress((void**)&buf2, g_buf2);
    cudaGetSymbolAddress((void**)&wb,   g_wb);
    float* x1f = (float*)buf2;

    const int GSM = 73728;
    cudaFuncSetAttribute(attn_k, cudaFuncAttributeMaxDynamicSharedMemorySize, 65792);
    cudaFuncSetAttribute(gemm_tc<128, 0>, cudaFuncAttributeMaxDynamicSharedMemorySize, GSM);
    cudaFuncSetAttribute(gemm_tc<256, 2>, cudaFuncAttributeMaxDynamicSharedMemorySize, GSM);
    cudaFuncSetAttribute(gemm_tc<128, 1>, cudaFuncAttributeMaxDynamicSharedMemorySize, GSM);
    cudaFuncSetAttribute(gemm_tc<128, 3>, cudaFuncAttributeMaxDynamicSharedMemorySize, GSM);

    // weights -> bf16
    wcvt_k<<<704, 256>>>(w_h1, w_p1, w_h2, w_p2, wb);

    // 1. LN1: x NCHW -> hn NHWC bf16
    ln1_k<<<512, 256>>>(x, n1w, n1b, hn);

    // 2. hidden = hn @ w_h1^T  -> buf1 [M,768] bf16
    gemm_tc<128, 0><<<dim3(1024, 6), 256, GSM>>>(hn, wb, nullptr, nullptr, nullptr, buf1, 768);

    // 3. qkv = dw3x3(hidden) -> buf2 [M,768] bf16
    dw_k<768, false><<<dim3(256, 48, 2), 256>>>(buf1, w_dw1, buf2);

    // 4. va = v * LN2(patchconv(q,k)) -> buf1 [M,256] bf16
    attn_k<<<dim3(1024, 1, 2), 256, 65792>>>(buf2, n2w, n2b, buf1);

    // 5. x1 = x + scale1 * (va @ w_p1^T) -> buf2 as fp32 NHWC [M,128]
    gemm_tc<256, 2><<<dim3(1024, 1), 256, GSM>>>(buf1, wb + 98304, nullptr, x, sc1, x1f, 128);

    // 6. LN3: x1 -> hn bf16 NHWC
    ln3_k<<<16384, 256>>>(x1f, n3w, n3b, hn);

    // 7. g = hn @ w_h2^T + b_h2 -> buf1 [M,256] bf16
    gemm_tc<128, 1><<<dim3(1024, 2), 256, GSM>>>(hn, wb + 131072, b_h2, nullptr, nullptr, buf1, 256);

    // 8. mgate = dw(g)[0:128] * dw(g)[128:256] -> hn [M,128] bf16
    dw_k<256, true><<<dim3(256, 8, 2), 256>>>(buf1, w_dw2, hn);

    // 9. out = x1 + scale2 * (mgate @ w_p2^T) -> d_out NCHW fp32
    gemm_tc<128, 3><<<dim3(1024, 1), 256, GSM>>>(hn, wb + 163840, nullptr, x1f, sc2, out, 128);
}

// round 14
// speedup vs baseline: 1.0051x; 1.0021x over previous
#include <cuda_runtime.h>
#include <cuda_bf16.h>
#include <cstdint>

// ===========================================================================
// NHWC bf16 pipeline with tensor-core (mma.sync bf16) GEMMs.
// R10: dw_k staging via 4-px register transpose + STS.128 (wavefront cut);
//      attn_k inner product in packed fma.rn.f32x2 (FMA instr halved).
// ===========================================================================

#define NPIX 65536           // per image
#define MTOT 131072L         // total pixels (batch 2)

typedef unsigned long long u64;

__device__ __align__(16) __nv_bfloat16 g_hn[MTOT * 128];    // LN outs / mgate
__device__ __align__(16) __nv_bfloat16 g_buf1[MTOT * 768];  // hidden / va / g
__device__ __align__(16) __nv_bfloat16 g_buf2[MTOT * 768];  // qkv / x1(fp32)
__device__ __align__(16) __nv_bfloat16 g_wb[180224];        // bf16 weights

__device__ __forceinline__ unsigned pack_bf(float a, float b) {
    __nv_bfloat162 h = __float22bfloat162_rn(make_float2(a, b));
    return *(unsigned*)&h;
}
__device__ __forceinline__ float2 unpack_bf(unsigned u) {
    __nv_bfloat162 h = *(__nv_bfloat162*)&u;
    return make_float2(__bfloat162float(h.x), __bfloat162float(h.y));
}
__device__ __forceinline__ uint32_t smem_u32(const void* p) {
    return (uint32_t)__cvta_generic_to_shared(p);
}
__device__ __forceinline__ void cp16(void* dst, const void* src) {
    asm volatile("cp.async.cg.shared.global [%0], [%1], 16;"
                 :: "r"(smem_u32(dst)), "l"(src));
}
// bf16x2 -> packed f32x2 (bf16 widens by <<16; no cvt needed)
__device__ __forceinline__ u64 bf2_to_f32x2(unsigned u) {
    unsigned lo = u << 16, hi = u & 0xffff0000u;
    u64 d;
    asm("mov.b64 %0, {%1,%2};" : "=l"(d) : "r"(lo), "r"(hi));
    return d;
}
#define FMA_F32X2(d, a, b) \
    asm("fma.rn.f32x2 %0, %1, %2, %0;" : "+l"(d) : "l"(a), "l"(b))

// ---------------------------------------------------------------------------
// Weight conversion fp32 -> bf16 (once per launch; tiny)
// ---------------------------------------------------------------------------
__global__ void wcvt_k(const float* __restrict__ w1, const float* __restrict__ w2,
                       const float* __restrict__ w3, const float* __restrict__ w4,
                       __nv_bfloat16* __restrict__ o)
{
    int i = blockIdx.x * 256 + threadIdx.x;
    if (i < 98304)       o[i] = __float2bfloat16(w1[i]);
    else if (i < 131072) o[i] = __float2bfloat16(w2[i - 98304]);
    else if (i < 163840) o[i] = __float2bfloat16(w3[i - 131072]);
    else if (i < 180224) o[i] = __float2bfloat16(w4[i - 163840]);
}

// ---------------------------------------------------------------------------
// LN1: x NCHW fp32 -> y NHWC bf16 (C=128).
// ---------------------------------------------------------------------------
__global__ __launch_bounds__(256) void ln1_k(const float* __restrict__ x,
                                             const float* __restrict__ g,
                                             const float* __restrict__ b,
                                             __nv_bfloat16* __restrict__ y)
{
    __shared__ __nv_bfloat16 st[256 * 18];
    int t = threadIdx.x;
    long gp0 = (long)blockIdx.x * 256;
    long gp = gp0 + t;
    int bb = (int)(gp >> 16);
    int p  = (int)(gp & 65535);
    const float* xp = x + (long)bb * 128 * NPIX + p;

    float s = 0.f, s2 = 0.f;
    for (int c = 0; c < 128; c++) {
        float v = xp[(long)c * NPIX];
        s += v; s2 += v * v;
    }
    float m = s * (1.f / 128.f);
    float r = rsqrtf(s2 * (1.f / 128.f) - m * m + 1e-6f);

    for (int c0 = 0; c0 < 128; c0 += 16) {
#pragma unroll
        for (int cc = 0; cc < 16; cc++) {
            float v = xp[(long)(c0 + cc) * NPIX];
            st[t * 18 + cc] = __float2bfloat16((v - m) * r * g[c0 + cc] + b[c0 + cc]);
        }
        __syncthreads();
        for (int it = 0; it < 8; it++) {
            int lin = it * 256 + t;
            int pl = lin >> 3, cw = lin & 7;
            unsigned v = *(unsigned*)&st[pl * 18 + cw * 2];
            *(unsigned*)(y + (gp0 + pl) * 128 + c0 + cw * 2) = v;
        }
        __syncthreads();
    }
}

// ---------------------------------------------------------------------------
// LN3: x1 NHWC fp32 -> y NHWC bf16 (C=128). Warp per pixel.
// ---------------------------------------------------------------------------
__global__ __launch_bounds__(256) void ln3_k(const float* __restrict__ x,
                                             const float* __restrict__ g,
                                             const float* __restrict__ b,
                                             __nv_bfloat16* __restrict__ y)
{
    int t = threadIdx.x, lane = t & 31, w = t >> 5;
    long p = (long)blockIdx.x * 8 + w;
    float4 v = *(const float4*)&x[p * 128 + lane * 4];
    float s = v.x + v.y + v.z + v.w;
    float s2 = v.x * v.x + v.y * v.y + v.z * v.z + v.w * v.w;
#pragma unroll
    for (int o = 16; o; o >>= 1) {
        s  += __shfl_xor_sync(0xffffffffu, s, o);
        s2 += __shfl_xor_sync(0xffffffffu, s2, o);
    }
    float m = s * (1.f / 128.f);
    float r = rsqrtf(s2 * (1.f / 128.f) - m * m + 1e-6f);
    int c = lane * 4;
    float o0 = (v.x - m) * r * g[c]     + b[c];
    float o1 = (v.y - m) * r * g[c + 1] + b[c + 1];
    float o2 = (v.z - m) * r * g[c + 2] + b[c + 2];
    float o3 = (v.w - m) * r * g[c + 3] + b[c + 3];
    uint2 u = make_uint2(pack_bf(o0, o1), pack_bf(o2, o3));
    *(uint2*)(y + p * 128 + c) = u;
}

// ---------------------------------------------------------------------------
// Tensor-core GEMM with cp.async 2-stage double buffering.
//   A: NHWC bf16 activations [M, K], B: bf16 weights [Ntot, K]
// EPI 0: bf16 out | 1: bf16 out + bias | 2: fp32 NHWC = x_nchw + S*acc |
// EPI 3: fp32 NCHW = x1_nhwc + S*acc.
// Block tile 128x128x64, 8 warps. Dynamic smem 73728 B.
// ---------------------------------------------------------------------------
template <int K, int EPI>
__global__ __launch_bounds__(256) void gemm_tc(
    const __nv_bfloat16* __restrict__ A, const __nv_bfloat16* __restrict__ B,
    const float* __restrict__ bias, const float* __restrict__ R,
    const float* __restrict__ S, void* __restrict__ Yv, int Ntot)
{
    constexpr int LDS_ = 72;
    constexpr int MATSZ = 128 * LDS_;        // 9216 elems
    constexpr int STAGE = 2 * MATSZ;         // A+B per stage
    extern __shared__ __nv_bfloat16 sm[];

    int t = threadIdx.x;
    long m0 = (long)blockIdx.x * 128;
    int n0 = blockIdx.y * 128;
    int wid = t >> 5, lane = t & 31;
    int wm = (wid & 3) * 32, wn = (wid >> 2) * 64;

    float acc[2][8][4];
#pragma unroll
    for (int i = 0; i < 2; i++)
#pragma unroll
        for (int j = 0; j < 8; j++)
#pragma unroll
            for (int q = 0; q < 4; q++) acc[i][j][q] = 0.f;

    int lrow = t >> 3, lcol = (t & 7) * 8;

    auto load_stage = [&](int k0, int s) {
        __nv_bfloat16* As_ = sm + s * STAGE;
        __nv_bfloat16* Bs_ = As_ + MATSZ;
#pragma unroll
        for (int pp = 0; pp < 4; pp++) {
            int row = pp * 32 + lrow;
            cp16(&As_[row * LDS_ + lcol], &A[(m0 + row) * K + k0 + lcol]);
            cp16(&Bs_[row * LDS_ + lcol], &B[(long)(n0 + row) * K + k0 + lcol]);
        }
        asm volatile("cp.async.commit_group;");
    };

    constexpr int NSTEP = K / 64;
    load_stage(0, 0);

#pragma unroll
    for (int st = 0; st < NSTEP; st++) {
        if (st + 1 < NSTEP) {
            load_stage((st + 1) * 64, (st + 1) & 1);
            asm volatile("cp.async.wait_group 1;");
        } else {
            asm volatile("cp.async.wait_group 0;");
        }
        __syncthreads();

        const __nv_bfloat16* As_ = sm + (st & 1) * STAGE;
        const __nv_bfloat16* Bs_ = As_ + MATSZ;

#pragma unroll
        for (int kk = 0; kk < 4; kk++) {
            uint32_t a[2][4], bf[8][2];
#pragma unroll
            for (int mi = 0; mi < 2; mi++) {
                uint32_t addr = smem_u32(
                    &As_[(wm + mi * 16 + (lane & 15)) * LDS_ + kk * 16 + (lane >> 4) * 8]);
                asm volatile("ldmatrix.sync.aligned.m8n8.x4.shared.b16 {%0,%1,%2,%3}, [%4];"
                             : "=r"(a[mi][0]), "=r"(a[mi][1]), "=r"(a[mi][2]), "=r"(a[mi][3])
                             : "r"(addr));
            }
#pragma unroll
            for (int nb = 0; nb < 4; nb++) {
                int row = wn + nb * 16 + ((lane >> 4) << 3) + (lane & 7);
                int col = kk * 16 + ((lane >> 3) & 1) * 8;
                uint32_t addr = smem_u32(&Bs_[row * LDS_ + col]);
                uint32_t r0, r1, r2, r3;
                asm volatile("ldmatrix.sync.aligned.m8n8.x4.shared.b16 {%0,%1,%2,%3}, [%4];"
                             : "=r"(r0), "=r"(r1), "=r"(r2), "=r"(r3) : "r"(addr));
                bf[nb * 2][0] = r0;     bf[nb * 2][1] = r1;
                bf[nb * 2 + 1][0] = r2; bf[nb * 2 + 1][1] = r3;
            }
#pragma unroll
            for (int mi = 0; mi < 2; mi++)
#pragma unroll
                for (int nj = 0; nj < 8; nj++) {
                    asm volatile(
                        "mma.sync.aligned.m16n8k16.row.col.f32.bf16.bf16.f32 "
                        "{%0,%1,%2,%3}, {%4,%5,%6,%7}, {%8,%9}, {%0,%1,%2,%3};"
                        : "+f"(acc[mi][nj][0]), "+f"(acc[mi][nj][1]),
                          "+f"(acc[mi][nj][2]), "+f"(acc[mi][nj][3])
                        : "r"(a[mi][0]), "r"(a[mi][1]), "r"(a[mi][2]), "r"(a[mi][3]),
                          "r"(bf[nj][0]), "r"(bf[nj][1]));
                }
        }
        __syncthreads();
    }

    int g = lane >> 2, tg = lane & 3;
#pragma unroll
    for (int mi = 0; mi < 2; mi++) {
#pragma unroll
        for (int nj = 0; nj < 8; nj++) {
            int col = n0 + wn + nj * 8 + tg * 2;
#pragma unroll
            for (int half = 0; half < 2; half++) {
                long row = m0 + wm + mi * 16 + g + half * 8;
                float v0 = acc[mi][nj][half * 2];
                float v1 = acc[mi][nj][half * 2 + 1];
                if (EPI == 0 || EPI == 1) {
                    if (EPI == 1) { v0 += bias[col]; v1 += bias[col + 1]; }
                    *(unsigned*)((__nv_bfloat16*)Yv + row * Ntot + col) = pack_bf(v0, v1);
                } else if (EPI == 2) {
                    int bb = (int)(row >> 16), p = (int)(row & 65535);
                    float r0 = R[((long)(bb * 128 + col)) * NPIX + p];
                    float r1 = R[((long)(bb * 128 + col + 1)) * NPIX + p];
                    float2 o = make_float2(r0 + S[col] * v0, r1 + S[col + 1] * v1);
                    *(float2*)((float*)Yv + row * 128 + col) = o;
                } else {  // EPI 3
                    int bb = (int)(row >> 16), p = (int)(row & 65535);
                    float2 rr = *(const float2*)&R[row * 128 + col];
                    ((float*)Yv)[((long)(bb * 128 + col)) * NPIX + p]     = rr.x + S[col] * v0;
                    ((float*)Yv)[((long)(bb * 128 + col + 1)) * NPIX + p] = rr.y + S[col + 1] * v1;
                }
            }
        }
    }
}

// ---------------------------------------------------------------------------
// Depthwise 3x3 NHWC bf16, SAME padding. Tile 8x32 px, 16 channels per block.
// Channel-pair slabs (conflict-free compute LDS): in_s[h][cg][row*36+col].
// R10 staging: 4-px items, register transpose, one STS.128 per slab
// ({px0..px3}), 16B-aligned (po = ry*36 + ri*4).
// GATE: two channel halves, writes their product (FFN gate).
// ---------------------------------------------------------------------------
template <int C, bool GATE>
__global__ __launch_bounds__(256) void dw_k(const __nv_bfloat16* __restrict__ X,
                                            const float* __restrict__ Wd,
                                            __nv_bfloat16* __restrict__ Y)
{
    constexpr int NH = GATE ? 2 : 1;
    __shared__ unsigned in_s[NH][8][364];   // 8 slabs x (10 rows * 36 + pad)
    __shared__ float w_s[NH][9][16];

    int t = threadIdx.x;
    int bx = blockIdx.x;
    int ty = bx >> 3, tx = bx & 7;
    int c0 = blockIdx.y * 16;
    long ibase = (long)blockIdx.z * NPIX;

    for (int i = t; i < NH * 144; i += 256) {
        int h = i / 144, j = i % 144, ch = j / 9, tap = j % 9;
        w_s[h][tap][ch] = Wd[(c0 + h * 128 + ch) * 9 + tap];
    }
    // stage 10x34 halo as 4-px items: 90 items, register transpose, STS.128
    for (int lin = t; lin < 90; lin += 256) {
        int ry = lin / 9, ri = lin % 9;
        int rx0 = ri * 4;
        int yy = ty * 8 + ry - 1;
        bool oky = (yy >= 0 && yy < 256);
        int po = ry * 36 + rx0;
#pragma unroll
        for (int h = 0; h < NH; h++) {
            unsigned vv[4][8];
#pragma unroll
            for (int p = 0; p < 4; p++) {
                int xx = tx * 32 + rx0 + p - 1;
                uint4 v0 = make_uint4(0,0,0,0), v1 = make_uint4(0,0,0,0);
                if (oky && xx >= 0 && xx < 256 && rx0 + p < 34) {
                    const uint4* s = (const uint4*)(X + (ibase + yy * 256 + xx) * C + c0 + h * 128);
                    v0 = s[0]; v1 = s[1];
                }
                *(uint4*)&vv[p][0] = v0;
                *(uint4*)&vv[p][4] = v1;
            }
#pragma unroll
            for (int s = 0; s < 8; s++) {
                uint4 w = make_uint4(vv[0][s], vv[1][s], vv[2][s], vv[3][s]);
                *(uint4*)&in_s[h][s][po] = w;
            }
        }
    }
    __syncthreads();

    int oy = t >> 5;            // 0..7 output row
    int xg = (t >> 3) & 3;      // 0..3 x-group (8 px each)
    int cg = t & 7;             // 0..7 channel pair
    int ox0 = xg * 8;

    float2 acc[NH][8];
#pragma unroll
    for (int h = 0; h < NH; h++)
#pragma unroll
        for (int j = 0; j < 8; j++) acc[h][j] = make_float2(0.f, 0.f);

#pragma unroll
    for (int h = 0; h < NH; h++) {
        float2 wr[9];
#pragma unroll
        for (int tap = 0; tap < 9; tap++)
            wr[tap] = make_float2(w_s[h][tap][cg * 2], w_s[h][tap][cg * 2 + 1]);

#pragma unroll
        for (int ky = 0; ky < 3; ky++) {
            const unsigned* rp = &in_s[h][cg][(oy + ky) * 36 + ox0];
            uint4 va_ = *(const uint4*)rp;
            uint4 vb_ = *(const uint4*)(rp + 4);
            uint2 vc_ = *(const uint2*)(rp + 8);
            float2 f[10];
            f[0] = unpack_bf(va_.x); f[1] = unpack_bf(va_.y);
            f[2] = unpack_bf(va_.z); f[3] = unpack_bf(va_.w);
            f[4] = unpack_bf(vb_.x); f[5] = unpack_bf(vb_.y);
            f[6] = unpack_bf(vb_.z); f[7] = unpack_bf(vb_.w);
            f[8] = unpack_bf(vc_.x); f[9] = unpack_bf(vc_.y);
#pragma unroll
            for (int kx = 0; kx < 3; kx++) {
                float2 w = wr[ky * 3 + kx];
#pragma unroll
                for (int j = 0; j < 8; j++) {
                    acc[h][j].x += f[j + kx].x * w.x;
                    acc[h][j].y += f[j + kx].y * w.y;
                }
            }
        }
    }

    long opix = ibase + (ty * 8 + oy) * 256 + tx * 32 + ox0;
    if (!GATE) {
#pragma unroll
        for (int j = 0; j < 8; j++)
            *(unsigned*)(Y + (opix + j) * C + c0 + cg * 2) =
                pack_bf(acc[0][j].x, acc[0][j].y);
    } else {
#pragma unroll
        for (int j = 0; j < 8; j++)
            *(unsigned*)(Y + (opix + j) * 128 + c0 + cg * 2) =
                pack_bf(acc[0][j].x * acc[1][j].x, acc[0][j].y * acc[1][j].y);
    }
}

// ---------------------------------------------------------------------------
// Patch attention (8x8 circular conv of q,k) fused with LN2 and * v.
// R10: inner product in packed fma.rn.f32x2 (2 channels per FMA instr,
// bitwise-identical fp32 rounding).
// ---------------------------------------------------------------------------
__global__ __launch_bounds__(256) void attn_k(const __nv_bfloat16* __restrict__ qkv,
                                              const float* __restrict__ g2,
                                              const float* __restrict__ b2,
                                              __nv_bfloat16* __restrict__ va)
{
    extern __shared__ char smdyn[];
    unsigned* q_s = (unsigned*)smdyn;        // [64*128]
    unsigned* k_s = q_s + 64 * 128;          // [64*128]
    float* attn = (float*)smdyn;             // [64*257] alias
    __shared__ float red[64][4][2];

    int t = threadIdx.x;
    int bx = blockIdx.x;
    int py = bx >> 5, px = bx & 31;
    long ibase = (long)blockIdx.z * NPIX;

    for (int r = 0; r < 8; r++) {
        int lin = r * 256 + t;
        int pix = lin >> 5, c4 = lin & 31;
        long gpix = ibase + (py * 8 + (pix >> 3)) * 256 + px * 8 + (pix & 7);
        ((uint4*)q_s)[pix * 32 + c4] = __ldg((const uint4*)(qkv + gpix * 768) + c4);
        ((uint4*)k_s)[pix * 32 + c4] = __ldg((const uint4*)(qkv + gpix * 768 + 256) + c4);
    }
    __syncthreads();

    int cp = t & 127;
    int mg = t >> 7;
    u64 acc[4][8];
#pragma unroll
    for (int a = 0; a < 4; a++)
#pragma unroll
        for (int b = 0; b < 8; b++) acc[a][b] = 0ULL;

#pragma unroll
    for (int i = 0; i < 8; i++) {
        u64 qv[8];
#pragma unroll
        for (int jx = 0; jx < 8; jx++)
            qv[jx] = bf2_to_f32x2(q_s[(i * 8 + jx) * 128 + cp]);
#pragma unroll
        for (int mi = 0; mi < 4; mi++) {
            int m = mg + 2 * mi;
            int kr = (m - i) & 7;
            u64 kv[8];
#pragma unroll
            for (int j = 0; j < 8; j++)
                kv[j] = bf2_to_f32x2(k_s[(kr * 8 + j) * 128 + cp]);
#pragma unroll
            for (int jo = 0; jo < 8; jo++)
#pragma unroll
                for (int jx = 0; jx < 8; jx++)
                    FMA_F32X2(acc[mi][jo], qv[jx], kv[(jo - jx) & 7]);
        }
    }
    __syncthreads();

#pragma unroll
    for (int mi = 0; mi < 4; mi++) {
        int m = mg + 2 * mi;
#pragma unroll
        for (int jo = 0; jo < 8; jo++) {
            float lo, hi;
            asm("mov.b64 {%0,%1}, %2;" : "=f"(lo), "=f"(hi) : "l"(acc[mi][jo]));
            attn[(m * 8 + jo) * 257 + 2 * cp]     = lo;
            attn[(m * 8 + jo) * 257 + 2 * cp + 1] = hi;
        }
    }
    __syncthreads();

    int pix = t >> 2, q4 = t & 3;
    const float* ap = attn + pix * 257 + q4 * 64;
    float s = 0.f, s2 = 0.f;
#pragma unroll
    for (int i = 0; i < 64; i++) { float v = ap[i]; s += v; s2 += v * v; }
    red[pix][q4][0] = s; red[pix][q4][1] = s2;
    __syncthreads();
    s  = red[pix][0][0] + red[pix][1][0] + red[pix][2][0] + red[pix][3][0];
    s2 = red[pix][0][1] + red[pix][1][1] + red[pix][2][1] + red[pix][3][1];
    float m = s * (1.f / 256.f);
    float r = rsqrtf(s2 * (1.f / 256.f) - m * m + 1e-6f);

    long gpix = ibase + (py * 8 + (pix >> 3)) * 256 + px * 8 + (pix & 7);
    const __nv_bfloat16* vp = qkv + gpix * 768 + 512 + q4 * 64;
    __nv_bfloat16* op = va + gpix * 256 + q4 * 64;
#pragma unroll
    for (int i = 0; i < 64; i += 2) {
        int c = q4 * 64 + i;
        float a0 = (ap[i] - m) * r * __ldg(g2 + c) + __ldg(b2 + c);
        float a1 = (ap[i + 1] - m) * r * __ldg(g2 + c + 1) + __ldg(b2 + c + 1);
        float2 v = unpack_bf(*(const unsigned*)(vp + i));
        *(unsigned*)(op + i) = pack_bf(a0 * v.x, a1 * v.y);
    }
}

// ---------------------------------------------------------------------------

extern "C" void kernel_launch(void* const* d_in, const int* in_sizes, int n_in,
                              void* d_out, int out_size)
{
    const float* x     = (const float*)d_in[0];
    const float* n1w   = (const float*)d_in[1];
    const float* n1b   = (const float*)d_in[2];
    const float* w_h1  = (const float*)d_in[3];
    const float* w_dw1 = (const float*)d_in[4];
    const float* n2w   = (const float*)d_in[5];
    const float* n2b   = (const float*)d_in[6];
    const float* w_p1  = (const float*)d_in[7];
    const float* n3w   = (const float*)d_in[8];
    const float* n3b   = (const float*)d_in[9];
    const float* w_h2  = (const float*)d_in[10];
    const float* b_h2  = (const float*)d_in[11];
    const float* w_dw2 = (const float*)d_in[12];
    const float* w_p2  = (const float*)d_in[13];
    const float* sc1   = (const float*)d_in[14];
    const float* sc2   = (const float*)d_in[15];
    float* out = (float*)d_out;

    __nv_bfloat16 *hn, *buf1, *buf2, *wb;
    cudaGetSymbolAddress((void**)&hn,   g_hn);
    cudaGetSymbolAddress((void**)&buf1, g_buf1);
    cudaGetSymbolAddress((void**)&buf2, g_buf2);
    cudaGetSymbolAddress((void**)&wb,   g_wb);
    float* x1f = (float*)buf2;

    const int GSM = 73728;
    cudaFuncSetAttribute(attn_k, cudaFuncAttributeMaxDynamicSharedMemorySize, 65792);
    cudaFuncSetAttribute(gemm_tc<128, 0>, cudaFuncAttributeMaxDynamicSharedMemorySize, GSM);
    cudaFuncSetAttribute(gemm_tc<256, 2>, cudaFuncAttributeMaxDynamicSharedMemorySize, GSM);
    cudaFuncSetAttribute(gemm_tc<128, 1>, cudaFuncAttributeMaxDynamicSharedMemorySize, GSM);
    cudaFuncSetAttribute(gemm_tc<128, 3>, cudaFuncAttributeMaxDynamicSharedMemorySize, GSM);

    // weights -> bf16
    wcvt_k<<<704, 256>>>(w_h1, w_p1, w_h2, w_p2, wb);

    // 1. LN1: x NCHW -> hn NHWC bf16
    ln1_k<<<512, 256>>>(x, n1w, n1b, hn);

    // 2. hidden = hn @ w_h1^T  -> buf1 [M,768] bf16
    gemm_tc<128, 0><<<dim3(1024, 6), 256, GSM>>>(hn, wb, nullptr, nullptr, nullptr, buf1, 768);

    // 3. qkv = dw3x3(hidden) -> buf2 [M,768] bf16
    dw_k<768, false><<<dim3(256, 48, 2), 256>>>(buf1, w_dw1, buf2);

    // 4. va = v * LN2(patchconv(q,k)) -> buf1 [M,256] bf16
    attn_k<<<dim3(1024, 1, 2), 256, 65792>>>(buf2, n2w, n2b, buf1);

    // 5. x1 = x + scale1 * (va @ w_p1^T) -> buf2 as fp32 NHWC [M,128]
    gemm_tc<256, 2><<<dim3(1024, 1), 256, GSM>>>(buf1, wb + 98304, nullptr, x, sc1, x1f, 128);

    // 6. LN3: x1 -> hn bf16 NHWC
    ln3_k<<<16384, 256>>>(x1f, n3w, n3b, hn);

    // 7. g = hn @ w_h2^T + b_h2 -> buf1 [M,256] bf16
    gemm_tc<128, 1><<<dim3(1024, 2), 256, GSM>>>(hn, wb + 131072, b_h2, nullptr, nullptr, buf1, 256);

    // 8. mgate = dw(g)[0:128] * dw(g)[128:256] -> hn [M,128] bf16
    dw_k<256, true><<<dim3(256, 8, 2), 256>>>(buf1, w_dw2, hn);

    // 9. out = x1 + scale2 * (mgate @ w_p2^T) -> d_out NCHW fp32
    gemm_tc<128, 3><<<dim3(1024, 1), 256, GSM>>>(hn, wb + 163840, nullptr, x1f, sc2, out, 128);
}